// round 14
// baseline (speedup 1.0000x reference)
#include <cuda_runtime.h>
#include <math.h>

#define HD 4096
#define LD 4096
#define VD 128000
#define NPART (VD / 1024)     // 125 per-block lse partials (float4 stage A)

// ---------------- scratch (device globals; no allocations) ----------------
__device__ __align__(16) float g_log0[LD];         // attn logits partial seg0 (+bias)
__device__ __align__(16) float g_log1[LD];         // attn logits partial seg1
__device__ __align__(16) float g_attn_applied[HD]; // zeroed by K1, atomics in K2
__device__ __align__(16) float g_lstm_in[HD];      // zeroed by K1, atomics in K3
__device__ __align__(16) float g_gates[4 * HD];    // base by K1, += in K4 (1 writer)
__device__ __align__(16) float g_hnew[HD];
__device__ __align__(16) float g_word[VD];
__device__ float g_pmax[NPART];
__device__ float g_psum[NPART];
__device__ float g_lse_word;

// ---------------- 8-deep front-batched single-row dot (streaming weights) ---
// Proven-best form (R7 bench, 440.4). DO NOT restructure: dual-row (R6),
// manual pipelining (R8), and shorter per-warp streams (R13) all regressed.
__device__ __forceinline__ float dot_seg(const float4* __restrict__ a,
                                         const float4* __restrict__ v,
                                         int i0, int n4, int lane)
{
    float s = 0.0f;
    for (int base = i0 + lane; base < i0 + n4; base += 256) {
        float4 r[8];
        #pragma unroll
        for (int j = 0; j < 8; ++j) r[j] = __ldcs(a + base + j * 32);
        #pragma unroll
        for (int j = 0; j < 8; ++j) {
            float4 vv = v[base + j * 32];
            s += r[j].x * vv.x + r[j].y * vv.y + r[j].z * vv.z + r[j].w * vv.w;
        }
    }
    return s;
}

__device__ __forceinline__ float warp_sum(float s) {
    #pragma unroll
    for (int o = 16; o; o >>= 1) s += __shfl_xor_sync(0xFFFFFFFFu, s, o);
    return s;
}

__device__ __forceinline__ void lse_merge(float& m, float& s, float m2, float s2) {
    float M = fmaxf(m, m2);
    s = s * expf(m - M) + s2 * expf(m2 - M);
    m = M;
}

// ---------------- K1: attn logits (S=2) + W_hh@h gate base + scratch zeroing
// blocks [0, 1024): attn logits, warp = (row, seg)  -> g_log0/g_log1
// blocks [1024, 3072): hh gates, warp-per-row 8-deep -> g_gates (+b_hh+b_ih)
#define NA_BLOCKS 1024
__global__ __launch_bounds__(256) void phase1_kernel(
    const float* __restrict__ W_attn, const float* __restrict__ b_attn,
    const float* __restrict__ h0, const float* __restrict__ x0,
    const float* __restrict__ W_hh, const float* __restrict__ b_hh,
    const float* __restrict__ b_ih)
{
    int wid = threadIdx.x >> 5, lane = threadIdx.x & 31;
    if (blockIdx.x < 16) g_lstm_in[blockIdx.x * 256 + threadIdx.x] = 0.0f;
    else if (blockIdx.x < 32) g_attn_applied[(blockIdx.x - 16) * 256 + threadIdx.x] = 0.0f;

    if (blockIdx.x < NA_BLOCKS) {
        int w = blockIdx.x * 8 + wid;
        int row = w >> 1, seg = w & 1;
        const float4* a = (const float4*)(W_attn + (size_t)row * 2 * HD);
        const float4* b = a + HD / 4;
        int i0 = seg * (HD / 8);           // 512 float4s per segment
        float s = dot_seg(a, (const float4*)h0, i0, HD / 8, lane)
                + dot_seg(b, (const float4*)x0, i0, HD / 8, lane);
        s = warp_sum(s);
        if (lane == 0) {
            if (seg == 0) g_log0[row] = s + b_attn[row];
            else          g_log1[row] = s;
        }
    } else {
        int row = (blockIdx.x - NA_BLOCKS) * 8 + wid;   // [0, 4H)
        const float4* a = (const float4*)(W_hh + (size_t)row * HD);
        float s = dot_seg(a, (const float4*)h0, 0, HD / 4, lane);
        s = warp_sum(s);
        if (lane == 0) g_gates[row] = s + b_hh[row] + b_ih[row];
    }
}

// ---------------- K2: per-block online LSE + attn_applied slice -------------
__global__ __launch_bounds__(256) void attn_applied_kernel(const float* __restrict__ enc) {
    __shared__ float smm[32], sms[32];
    __shared__ float wsh[16];
    int t = threadIdx.x;
    int lane = t & 31, wid = t >> 5;

    float m = -1e30f, s = 0.0f;
    for (int i = t; i < LD; i += 256) {
        float v = g_log0[i] + g_log1[i];
        if (v > m) { s = s * expf(m - v) + 1.0f; m = v; }
        else        s += expf(v - m);
    }
    #pragma unroll
    for (int o = 16; o; o >>= 1)
        lse_merge(m, s, __shfl_xor_sync(0xFFFFFFFFu, m, o),
                        __shfl_xor_sync(0xFFFFFFFFu, s, o));
    if (lane == 0) { smm[wid] = m; sms[wid] = s; }
    __syncthreads();
    if (wid == 0) {
        float mm = (lane < 8) ? smm[lane] : -1e30f;
        float ss = (lane < 8) ? sms[lane] : 0.0f;
        #pragma unroll
        for (int o = 4; o; o >>= 1)
            lse_merge(mm, ss, __shfl_xor_sync(0xFFFFFFFFu, mm, o),
                              __shfl_xor_sync(0xFFFFFFFFu, ss, o));
        if (lane == 0) { smm[0] = mm; sms[0] = ss; }
    }
    __syncthreads();
    float lse = smm[0] + logf(sms[0]);

    int l0 = blockIdx.y * 16;
    if (t < 16) wsh[t] = g_log0[l0 + t] + g_log1[l0 + t] - lse;
    __syncthreads();

    int c4 = blockIdx.x * 256 + t;                   // float4 column [0,1024)
    const float4* e = (const float4*)enc;
    float4 acc = make_float4(0.f, 0.f, 0.f, 0.f);
    #pragma unroll
    for (int j = 0; j < 16; ++j) {
        float w = wsh[j];
        float4 ev = __ldcs(e + (size_t)(l0 + j) * (HD / 4) + c4);
        acc.x += w * ev.x; acc.y += w * ev.y;
        acc.z += w * ev.z; acc.w += w * ev.w;
    }
    atomicAdd(&g_attn_applied[c4 * 4 + 0], acc.x);
    atomicAdd(&g_attn_applied[c4 * 4 + 1], acc.y);
    atomicAdd(&g_attn_applied[c4 * 4 + 2], acc.z);
    atomicAdd(&g_attn_applied[c4 * 4 + 3], acc.w);
}

// ---------------- K3: lstm_in += [x, attn_applied] @ W_comb^T + b  (S=2) ----
__global__ __launch_bounds__(256) void comb_kernel(
    const float* __restrict__ W_comb, const float* __restrict__ b_comb,
    const float* __restrict__ x0)
{
    int wid = threadIdx.x >> 5, lane = threadIdx.x & 31;
    int w = blockIdx.x * 8 + wid;          // grid 1024
    int row = w >> 1, seg = w & 1;
    const float4* a = (const float4*)(W_comb + (size_t)row * 2 * HD);
    const float4* b = a + HD / 4;
    int i0 = seg * (HD / 8);
    float s = dot_seg(a, (const float4*)x0, i0, HD / 8, lane)
            + dot_seg(b, (const float4*)g_attn_applied, i0, HD / 8, lane);
    s = warp_sum(s);
    if (lane == 0)
        atomicAdd(&g_lstm_in[row], s + (seg == 0 ? b_comb[row] : 0.0f));
}

// ---------------- K4: gates += W_ih @ lstm_in  (S=1, warp-per-row, 16 KB) ---
// wout-proven geometry: full-row streams. Single writer per row -> no atomics.
__global__ __launch_bounds__(256) void ih_kernel(const float* __restrict__ W_ih)
{
    int wid = threadIdx.x >> 5, lane = threadIdx.x & 31;
    int row = blockIdx.x * 8 + wid;        // grid 2048 -> rows [0, 4H)
    const float4* a = (const float4*)(W_ih + (size_t)row * HD);
    float s = dot_seg(a, (const float4*)g_lstm_in, 0, HD / 4, lane);
    s = warp_sum(s);
    if (lane == 0) g_gates[row] = g_gates[row] + s;   // base written by K1
}

// ---------------- K5: LSTM cell elementwise ----------------
__global__ void lstm_kernel(const float* __restrict__ c0) {
    int i = blockIdx.x * blockDim.x + threadIdx.x;
    if (i >= HD) return;
    float ig = g_gates[i];
    float fg = g_gates[i + HD];
    float gg = g_gates[i + 2 * HD];
    float og = g_gates[i + 3 * HD];
    float si = 1.0f / (1.0f + expf(-ig));
    float sf = 1.0f / (1.0f + expf(-fg));
    float so = 1.0f / (1.0f + expf(-og));
    float cn = sf * c0[i] + si * tanhf(gg);
    g_hnew[i] = so * tanhf(cn);
}

// ---------------- K6: word = h_new @ W_out^T + b_out  (proven form) ---------
__global__ __launch_bounds__(256) void wout_kernel(
    const float* __restrict__ W_out, const float* __restrict__ b_out)
{
    int wid = threadIdx.x >> 5, lane = threadIdx.x & 31;
    int row = blockIdx.x * 8 + wid;        // grid 16000
    const float4* a = (const float4*)(W_out + (size_t)row * HD);
    float s = dot_seg(a, (const float4*)g_hnew, 0, HD / 4, lane);
    s = warp_sum(s);
    if (lane == 0) g_word[row] = s + b_out[row];
}

// ---------------- K7: vocab lse stage A (float4, 125 blocks x 256) ----------
__global__ __launch_bounds__(256) void word_lse_partial_kernel() {
    __shared__ float smm[32], sms[32];
    int t = threadIdx.x;
    int lane = t & 31, wid = t >> 5;
    int i = blockIdx.x * 256 + t;          // 125*256 = 32000 float4s = VD
    float4 x = __ldcs((const float4*)g_word + i);
    float m = fmaxf(fmaxf(x.x, x.y), fmaxf(x.z, x.w));
    float s = expf(x.x - m) + expf(x.y - m) + expf(x.z - m) + expf(x.w - m);
    #pragma unroll
    for (int o = 16; o; o >>= 1)
        lse_merge(m, s, __shfl_xor_sync(0xFFFFFFFFu, m, o),
                        __shfl_xor_sync(0xFFFFFFFFu, s, o));
    if (lane == 0) { smm[wid] = m; sms[wid] = s; }
    __syncthreads();
    if (t == 0) {
        float mm = smm[0], ss = sms[0];
        #pragma unroll
        for (int j = 1; j < 8; ++j) lse_merge(mm, ss, smm[j], sms[j]);
        g_pmax[blockIdx.x] = mm; g_psum[blockIdx.x] = ss;
    }
}

// ---------------- K8: combine 125 lse partials (single block) ---------------
__global__ __launch_bounds__(128) void word_lse_final_kernel() {
    __shared__ float smm[4], sms[4];
    int t = threadIdx.x;
    int lane = t & 31, wid = t >> 5;
    float m = (t < NPART) ? g_pmax[t] : -1e30f;
    float s = (t < NPART) ? g_psum[t] : 0.0f;
    #pragma unroll
    for (int o = 16; o; o >>= 1)
        lse_merge(m, s, __shfl_xor_sync(0xFFFFFFFFu, m, o),
                        __shfl_xor_sync(0xFFFFFFFFu, s, o));
    if (lane == 0) { smm[wid] = m; sms[wid] = s; }
    __syncthreads();
    if (t == 0) {
        float mm = smm[0], ss = sms[0];
        #pragma unroll
        for (int j = 1; j < 4; ++j) lse_merge(mm, ss, smm[j], sms[j]);
        g_lse_word = mm + logf(ss);
    }
}

// ---------------- K9: out = word - lse (float4) ----------------
__global__ __launch_bounds__(256) void final_kernel(float* __restrict__ out) {
    int i = blockIdx.x * 256 + threadIdx.x;          // 125 blocks x 256 float4s
    float lse = g_lse_word;
    float4 x = ((const float4*)g_word)[i];
    x.x -= lse; x.y -= lse; x.z -= lse; x.w -= lse;
    ((float4*)out)[i] = x;
}

// ======================================================================
extern "C" void kernel_launch(void* const* d_in, const int* in_sizes, int n_in,
                              void* d_out, int out_size) {
    const float* enc    = (const float*)d_in[0];
    const float* h0     = (const float*)d_in[1];
    const float* c0     = (const float*)d_in[2];
    const float* x0     = (const float*)d_in[3];
    const float* W_attn = (const float*)d_in[4];
    const float* b_attn = (const float*)d_in[5];
    const float* W_comb = (const float*)d_in[6];
    const float* b_comb = (const float*)d_in[7];
    const float* W_ih   = (const float*)d_in[8];
    const float* b_ih   = (const float*)d_in[9];
    const float* W_hh   = (const float*)d_in[10];
    const float* b_hh   = (const float*)d_in[11];
    const float* W_out  = (const float*)d_in[12];
    const float* b_out  = (const float*)d_in[13];
    float* out = (float*)d_out;

    const int TPB = 256;

    // K1: attn logits (S=2, 1024 blks) + W_hh@h base (2048 blks) + zeroing
    phase1_kernel<<<NA_BLOCKS + (4 * HD) / 8, TPB>>>(W_attn, b_attn, h0, x0,
                                                     W_hh, b_hh, b_ih);
    // K2: per-block LSE + attn_applied   (64 MB, 1024 blocks)
    attn_applied_kernel<<<dim3(HD / 4 / TPB, 256), TPB>>>(enc);
    // K3: lstm_in = [x, attn_applied] @ W_comb^T + b   (S=2, 1024 blocks)
    comb_kernel<<<(2 * HD) / 8, TPB>>>(W_comb, b_comb, x0);
    // K4: gates += W_ih @ lstm_in   (S=1, full-row streams, 2048 blocks)
    ih_kernel<<<(4 * HD) / 8, TPB>>>(W_ih);
    // K5: LSTM cell
    lstm_kernel<<<HD / TPB, TPB>>>(c0);
    // K6: word = h_new @ W_out^T + b_out   (2.1 GB, 16000 blocks)
    wout_kernel<<<VD / 8, TPB>>>(W_out, b_out);
    // K7-8: logsumexp over V (float4 stage A: 125 blocks)
    word_lse_partial_kernel<<<NPART, TPB>>>();
    word_lse_final_kernel<<<1, 128>>>();
    // K9: out = word - lse (float4)
    final_kernel<<<NPART, TPB>>>(out);
}

// round 15
// speedup vs baseline: 1.0040x; 1.0040x over previous
#include <cuda_runtime.h>
#include <math.h>

#define HD 4096
#define LD 4096
#define VD 128000
#define NPART (VD / 1024)     // 125 per-block lse partials (float4 stage A)

// ---------------- scratch (device globals; no allocations) ----------------
__device__ __align__(16) float g_log0[LD];         // attn logits partial seg0 (+bias)
__device__ __align__(16) float g_log1[LD];         // attn logits partial seg1
__device__ __align__(16) float g_attn_applied[HD]; // zeroed by K1, atomics in K2
__device__ __align__(16) float g_lstm_in[HD];      // zeroed by K1, atomics in K3
__device__ __align__(16) float g_gates[4 * HD];    // base by K1, atomics in K4
__device__ __align__(16) float g_hnew[HD];
__device__ __align__(16) float g_word[VD];
__device__ float g_pmax[NPART];
__device__ float g_psum[NPART];
__device__ float g_lse_word;

// ---------------- 8-deep front-batched single-row dot (streaming weights) ---
// Proven-best inner loop (440.4 µs bench). DO NOT restructure the batch:
// dual-row (R6), manual pipelining (R8) regressed. Split-K OUTSIDE the batch
// is fine as long as each lane still issues 8 consecutive LDG.128.
__device__ __forceinline__ float dot_seg(const float4* __restrict__ a,
                                         const float4* __restrict__ v,
                                         int i0, int n4, int lane)
{
    float s = 0.0f;
    for (int base = i0 + lane; base < i0 + n4; base += 256) {
        float4 r[8];
        #pragma unroll
        for (int j = 0; j < 8; ++j) r[j] = __ldcs(a + base + j * 32);
        #pragma unroll
        for (int j = 0; j < 8; ++j) {
            float4 vv = v[base + j * 32];
            s += r[j].x * vv.x + r[j].y * vv.y + r[j].z * vv.z + r[j].w * vv.w;
        }
    }
    return s;
}

__device__ __forceinline__ float warp_sum(float s) {
    #pragma unroll
    for (int o = 16; o; o >>= 1) s += __shfl_xor_sync(0xFFFFFFFFu, s, o);
    return s;
}

__device__ __forceinline__ void lse_merge(float& m, float& s, float m2, float s2) {
    float M = fmaxf(m, m2);
    s = s * expf(m - M) + s2 * expf(m2 - M);
    m = M;
}

// ---------------- K1: attn logits (S=2) + W_hh@h gate base + scratch zeroing
// blocks [0, 1024): attn logits, warp = (row, seg)  -> g_log0/g_log1
// blocks [1024, 3072): hh gates, warp-per-row 8-deep -> g_gates (+b_hh+b_ih)
#define NA_BLOCKS 1024
__global__ __launch_bounds__(256) void phase1_kernel(
    const float* __restrict__ W_attn, const float* __restrict__ b_attn,
    const float* __restrict__ h0, const float* __restrict__ x0,
    const float* __restrict__ W_hh, const float* __restrict__ b_hh,
    const float* __restrict__ b_ih)
{
    int wid = threadIdx.x >> 5, lane = threadIdx.x & 31;
    if (blockIdx.x < 16) g_lstm_in[blockIdx.x * 256 + threadIdx.x] = 0.0f;
    else if (blockIdx.x < 32) g_attn_applied[(blockIdx.x - 16) * 256 + threadIdx.x] = 0.0f;

    if (blockIdx.x < NA_BLOCKS) {
        int w = blockIdx.x * 8 + wid;
        int row = w >> 1, seg = w & 1;
        const float4* a = (const float4*)(W_attn + (size_t)row * 2 * HD);
        const float4* b = a + HD / 4;
        int i0 = seg * (HD / 8);           // 512 float4s per segment
        float s = dot_seg(a, (const float4*)h0, i0, HD / 8, lane)
                + dot_seg(b, (const float4*)x0, i0, HD / 8, lane);
        s = warp_sum(s);
        if (lane == 0) {
            if (seg == 0) g_log0[row] = s + b_attn[row];
            else          g_log1[row] = s;
        }
    } else {
        int row = (blockIdx.x - NA_BLOCKS) * 8 + wid;   // [0, 4H)
        const float4* a = (const float4*)(W_hh + (size_t)row * HD);
        float s = dot_seg(a, (const float4*)h0, 0, HD / 4, lane);
        s = warp_sum(s);
        if (lane == 0) g_gates[row] = s + b_hh[row] + b_ih[row];
    }
}

// ---------------- K2: per-block online LSE + attn_applied slice -------------
__global__ __launch_bounds__(256) void attn_applied_kernel(const float* __restrict__ enc) {
    __shared__ float smm[32], sms[32];
    __shared__ float wsh[16];
    int t = threadIdx.x;
    int lane = t & 31, wid = t >> 5;

    float m = -1e30f, s = 0.0f;
    for (int i = t; i < LD; i += 256) {
        float v = g_log0[i] + g_log1[i];
        if (v > m) { s = s * expf(m - v) + 1.0f; m = v; }
        else        s += expf(v - m);
    }
    #pragma unroll
    for (int o = 16; o; o >>= 1)
        lse_merge(m, s, __shfl_xor_sync(0xFFFFFFFFu, m, o),
                        __shfl_xor_sync(0xFFFFFFFFu, s, o));
    if (lane == 0) { smm[wid] = m; sms[wid] = s; }
    __syncthreads();
    if (wid == 0) {
        float mm = (lane < 8) ? smm[lane] : -1e30f;
        float ss = (lane < 8) ? sms[lane] : 0.0f;
        #pragma unroll
        for (int o = 4; o; o >>= 1)
            lse_merge(mm, ss, __shfl_xor_sync(0xFFFFFFFFu, mm, o),
                              __shfl_xor_sync(0xFFFFFFFFu, ss, o));
        if (lane == 0) { smm[0] = mm; sms[0] = ss; }
    }
    __syncthreads();
    float lse = smm[0] + logf(sms[0]);

    int l0 = blockIdx.y * 16;
    if (t < 16) wsh[t] = g_log0[l0 + t] + g_log1[l0 + t] - lse;
    __syncthreads();

    int c4 = blockIdx.x * 256 + t;                   // float4 column [0,1024)
    const float4* e = (const float4*)enc;
    float4 acc = make_float4(0.f, 0.f, 0.f, 0.f);
    #pragma unroll
    for (int j = 0; j < 16; ++j) {
        float w = wsh[j];
        float4 ev = __ldcs(e + (size_t)(l0 + j) * (HD / 4) + c4);
        acc.x += w * ev.x; acc.y += w * ev.y;
        acc.z += w * ev.z; acc.w += w * ev.w;
    }
    atomicAdd(&g_attn_applied[c4 * 4 + 0], acc.x);
    atomicAdd(&g_attn_applied[c4 * 4 + 1], acc.y);
    atomicAdd(&g_attn_applied[c4 * 4 + 2], acc.z);
    atomicAdd(&g_attn_applied[c4 * 4 + 3], acc.w);
}

// ---------------- K3: lstm_in += [x, attn_applied] @ W_comb^T + b  (S=2) ----
__global__ __launch_bounds__(256) void comb_kernel(
    const float* __restrict__ W_comb, const float* __restrict__ b_comb,
    const float* __restrict__ x0)
{
    int wid = threadIdx.x >> 5, lane = threadIdx.x & 31;
    int w = blockIdx.x * 8 + wid;          // grid 1024
    int row = w >> 1, seg = w & 1;
    const float4* a = (const float4*)(W_comb + (size_t)row * 2 * HD);
    const float4* b = a + HD / 4;
    int i0 = seg * (HD / 8);
    float s = dot_seg(a, (const float4*)x0, i0, HD / 8, lane)
            + dot_seg(b, (const float4*)g_attn_applied, i0, HD / 8, lane);
    s = warp_sum(s);
    if (lane == 0)
        atomicAdd(&g_lstm_in[row], s + (seg == 0 ? b_comb[row] : 0.0f));
}

// ---------------- K4: gates += W_ih @ lstm_in  (S=4, 64 K warps) ------------
// Each lane still issues one full 8-deep batch (256 float4s per segment).
__global__ __launch_bounds__(256) void ih_kernel(const float* __restrict__ W_ih)
{
    int wid = threadIdx.x >> 5, lane = threadIdx.x & 31;
    int w = blockIdx.x * 8 + wid;          // grid 8192 -> (row, seg), seg in [0,4)
    int row = w >> 2, seg = w & 3;
    const float4* a = (const float4*)(W_ih + (size_t)row * HD);
    int i0 = seg * (HD / 16);              // 256 float4s per segment
    float s = dot_seg(a, (const float4*)g_lstm_in, i0, HD / 16, lane);
    s = warp_sum(s);
    if (lane == 0) atomicAdd(&g_gates[row], s);
}

// ---------------- K5: LSTM cell elementwise ----------------
__global__ void lstm_kernel(const float* __restrict__ c0) {
    int i = blockIdx.x * blockDim.x + threadIdx.x;
    if (i >= HD) return;
    float ig = g_gates[i];
    float fg = g_gates[i + HD];
    float gg = g_gates[i + 2 * HD];
    float og = g_gates[i + 3 * HD];
    float si = 1.0f / (1.0f + expf(-ig));
    float sf = 1.0f / (1.0f + expf(-fg));
    float so = 1.0f / (1.0f + expf(-og));
    float cn = sf * c0[i] + si * tanhf(gg);
    g_hnew[i] = so * tanhf(cn);
}

// ---------------- K6: word = h_new @ W_out^T + b_out  (proven form) ---------
__global__ __launch_bounds__(256) void wout_kernel(
    const float* __restrict__ W_out, const float* __restrict__ b_out)
{
    int wid = threadIdx.x >> 5, lane = threadIdx.x & 31;
    int row = blockIdx.x * 8 + wid;        // grid 16000
    const float4* a = (const float4*)(W_out + (size_t)row * HD);
    float s = dot_seg(a, (const float4*)g_hnew, 0, HD / 4, lane);
    s = warp_sum(s);
    if (lane == 0) g_word[row] = s + b_out[row];
}

// ---------------- K7: vocab lse stage A (float4, 125 blocks x 256) ----------
__global__ __launch_bounds__(256) void word_lse_partial_kernel() {
    __shared__ float smm[32], sms[32];
    int t = threadIdx.x;
    int lane = t & 31, wid = t >> 5;
    int i = blockIdx.x * 256 + t;          // 125*256 = 32000 float4s = VD
    float4 x = __ldcs((const float4*)g_word + i);
    float m = fmaxf(fmaxf(x.x, x.y), fmaxf(x.z, x.w));
    float s = expf(x.x - m) + expf(x.y - m) + expf(x.z - m) + expf(x.w - m);
    #pragma unroll
    for (int o = 16; o; o >>= 1)
        lse_merge(m, s, __shfl_xor_sync(0xFFFFFFFFu, m, o),
                        __shfl_xor_sync(0xFFFFFFFFu, s, o));
    if (lane == 0) { smm[wid] = m; sms[wid] = s; }
    __syncthreads();
    if (t == 0) {
        float mm = smm[0], ss = sms[0];
        #pragma unroll
        for (int j = 1; j < 8; ++j) lse_merge(mm, ss, smm[j], sms[j]);
        g_pmax[blockIdx.x] = mm; g_psum[blockIdx.x] = ss;
    }
}

// ---------------- K8: combine 125 lse partials (single block) ---------------
__global__ __launch_bounds__(128) void word_lse_final_kernel() {
    __shared__ float smm[4], sms[4];
    int t = threadIdx.x;
    int lane = t & 31, wid = t >> 5;
    float m = (t < NPART) ? g_pmax[t] : -1e30f;
    float s = (t < NPART) ? g_psum[t] : 0.0f;
    #pragma unroll
    for (int o = 16; o; o >>= 1)
        lse_merge(m, s, __shfl_xor_sync(0xFFFFFFFFu, m, o),
                        __shfl_xor_sync(0xFFFFFFFFu, s, o));
    if (lane == 0) { smm[wid] = m; sms[wid] = s; }
    __syncthreads();
    if (t == 0) {
        float mm = smm[0], ss = sms[0];
        #pragma unroll
        for (int j = 1; j < 4; ++j) lse_merge(mm, ss, smm[j], sms[j]);
        g_lse_word = mm + logf(ss);
    }
}

// ---------------- K9: out = word - lse (float4) ----------------
__global__ __launch_bounds__(256) void final_kernel(float* __restrict__ out) {
    int i = blockIdx.x * 256 + threadIdx.x;          // 125 blocks x 256 float4s
    float lse = g_lse_word;
    float4 x = ((const float4*)g_word)[i];
    x.x -= lse; x.y -= lse; x.z -= lse; x.w -= lse;
    ((float4*)out)[i] = x;
}

// ======================================================================
extern "C" void kernel_launch(void* const* d_in, const int* in_sizes, int n_in,
                              void* d_out, int out_size) {
    const float* enc    = (const float*)d_in[0];
    const float* h0     = (const float*)d_in[1];
    const float* c0     = (const float*)d_in[2];
    const float* x0     = (const float*)d_in[3];
    const float* W_attn = (const float*)d_in[4];
    const float* b_attn = (const float*)d_in[5];
    const float* W_comb = (const float*)d_in[6];
    const float* b_comb = (const float*)d_in[7];
    const float* W_ih   = (const float*)d_in[8];
    const float* b_ih   = (const float*)d_in[9];
    const float* W_hh   = (const float*)d_in[10];
    const float* b_hh   = (const float*)d_in[11];
    const float* W_out  = (const float*)d_in[12];
    const float* b_out  = (const float*)d_in[13];
    float* out = (float*)d_out;

    const int TPB = 256;

    // K1: attn logits (S=2, 1024 blks) + W_hh@h base (2048 blks) + zeroing
    phase1_kernel<<<NA_BLOCKS + (4 * HD) / 8, TPB>>>(W_attn, b_attn, h0, x0,
                                                     W_hh, b_hh, b_ih);
    // K2: per-block LSE + attn_applied   (64 MB, 1024 blocks)
    attn_applied_kernel<<<dim3(HD / 4 / TPB, 256), TPB>>>(enc);
    // K3: lstm_in = [x, attn_applied] @ W_comb^T + b   (S=2, 1024 blocks)
    comb_kernel<<<(2 * HD) / 8, TPB>>>(W_comb, b_comb, x0);
    // K4: gates += W_ih @ lstm_in   (S=4, 8192 blocks, 64 K warps)
    ih_kernel<<<(4 * 4 * HD) / 8, TPB>>>(W_ih);
    // K5: LSTM cell
    lstm_kernel<<<HD / TPB, TPB>>>(c0);
    // K6: word = h_new @ W_out^T + b_out   (2.1 GB, 16000 blocks)
    wout_kernel<<<VD / 8, TPB>>>(W_out, b_out);
    // K7-8: logsumexp over V (float4 stage A: 125 blocks)
    word_lse_partial_kernel<<<NPART, TPB>>>();
    word_lse_final_kernel<<<1, 128>>>();
    // K9: out = word - lse (float4)
    final_kernel<<<NPART, TPB>>>(out);
}

// round 17
// speedup vs baseline: 1.0191x; 1.0150x over previous
#include <cuda_runtime.h>
#include <math.h>

#define HD 4096
#define LD 4096
#define VD 128000
#define NPART (VD / 1024)     // 125 per-block lse partials (float4 stage A)

// ---------------- scratch (device globals; no allocations) ----------------
__device__ __align__(16) float g_log0[LD];         // attn logits partial seg0 (+bias)
__device__ __align__(16) float g_log1[LD];         // attn logits partial seg1
__device__ __align__(16) float g_attn_applied[HD]; // zeroed by K1, atomics in K2
__device__ __align__(16) float g_lstm_in[HD];      // zeroed by K1, atomics in K3
__device__ __align__(16) float g_gates[4 * HD];    // base by K1, atomics in K4
__device__ __align__(16) float g_hnew[HD];
__device__ __align__(16) float g_word[VD];
__device__ float g_pmax[NPART];
__device__ float g_psum[NPART];
__device__ float g_lse_word;

// ---------------- 8-deep front-batched single-row dot (streaming weights) ---
// Measured-best inner loop (440.4 µs, R7). Ledger of falsified alternatives:
// dual-row (R6: -1.4%), manual double-buffer (R8: -1.4%), shorter streams
// (R13: -1%), S=1 long streams (R14: -1.9%), S=4 more warps (R15: -1.5%).
// This form + __ldcs is the plateau. Leave it alone.
__device__ __forceinline__ float dot_seg(const float4* __restrict__ a,
                                         const float4* __restrict__ v,
                                         int i0, int n4, int lane)
{
    float s = 0.0f;
    for (int base = i0 + lane; base < i0 + n4; base += 256) {
        float4 r[8];
        #pragma unroll
        for (int j = 0; j < 8; ++j) r[j] = __ldcs(a + base + j * 32);
        #pragma unroll
        for (int j = 0; j < 8; ++j) {
            float4 vv = v[base + j * 32];
            s += r[j].x * vv.x + r[j].y * vv.y + r[j].z * vv.z + r[j].w * vv.w;
        }
    }
    return s;
}

__device__ __forceinline__ float warp_sum(float s) {
    #pragma unroll
    for (int o = 16; o; o >>= 1) s += __shfl_xor_sync(0xFFFFFFFFu, s, o);
    return s;
}

__device__ __forceinline__ void lse_merge(float& m, float& s, float m2, float s2) {
    float M = fmaxf(m, m2);
    s = s * expf(m - M) + s2 * expf(m2 - M);
    m = M;
}

// ---------------- K1: attn logits (S=2) + W_hh@h gate base + scratch zeroing
// blocks [0, 1024): attn logits, warp = (row, seg)  -> g_log0/g_log1
// blocks [1024, 3072): hh gates, warp-per-row 8-deep -> g_gates (+b_hh+b_ih)
#define NA_BLOCKS 1024
__global__ __launch_bounds__(256) void phase1_kernel(
    const float* __restrict__ W_attn, const float* __restrict__ b_attn,
    const float* __restrict__ h0, const float* __restrict__ x0,
    const float* __restrict__ W_hh, const float* __restrict__ b_hh,
    const float* __restrict__ b_ih)
{
    int wid = threadIdx.x >> 5, lane = threadIdx.x & 31;
    if (blockIdx.x < 16) g_lstm_in[blockIdx.x * 256 + threadIdx.x] = 0.0f;
    else if (blockIdx.x < 32) g_attn_applied[(blockIdx.x - 16) * 256 + threadIdx.x] = 0.0f;

    if (blockIdx.x < NA_BLOCKS) {
        int w = blockIdx.x * 8 + wid;
        int row = w >> 1, seg = w & 1;
        const float4* a = (const float4*)(W_attn + (size_t)row * 2 * HD);
        const float4* b = a + HD / 4;
        int i0 = seg * (HD / 8);           // 512 float4s per segment
        float s = dot_seg(a, (const float4*)h0, i0, HD / 8, lane)
                + dot_seg(b, (const float4*)x0, i0, HD / 8, lane);
        s = warp_sum(s);
        if (lane == 0) {
            if (seg == 0) g_log0[row] = s + b_attn[row];
            else          g_log1[row] = s;
        }
    } else {
        int row = (blockIdx.x - NA_BLOCKS) * 8 + wid;   // [0, 4H)
        const float4* a = (const float4*)(W_hh + (size_t)row * HD);
        float s = dot_seg(a, (const float4*)h0, 0, HD / 4, lane);
        s = warp_sum(s);
        if (lane == 0) g_gates[row] = s + b_hh[row] + b_ih[row];
    }
}

// ---------------- K2: per-block online LSE + attn_applied slice -------------
__global__ __launch_bounds__(256) void attn_applied_kernel(const float* __restrict__ enc) {
    __shared__ float smm[32], sms[32];
    __shared__ float wsh[16];
    int t = threadIdx.x;
    int lane = t & 31, wid = t >> 5;

    float m = -1e30f, s = 0.0f;
    for (int i = t; i < LD; i += 256) {
        float v = g_log0[i] + g_log1[i];
        if (v > m) { s = s * expf(m - v) + 1.0f; m = v; }
        else        s += expf(v - m);
    }
    #pragma unroll
    for (int o = 16; o; o >>= 1)
        lse_merge(m, s, __shfl_xor_sync(0xFFFFFFFFu, m, o),
                        __shfl_xor_sync(0xFFFFFFFFu, s, o));
    if (lane == 0) { smm[wid] = m; sms[wid] = s; }
    __syncthreads();
    if (wid == 0) {
        float mm = (lane < 8) ? smm[lane] : -1e30f;
        float ss = (lane < 8) ? sms[lane] : 0.0f;
        #pragma unroll
        for (int o = 4; o; o >>= 1)
            lse_merge(mm, ss, __shfl_xor_sync(0xFFFFFFFFu, mm, o),
                              __shfl_xor_sync(0xFFFFFFFFu, ss, o));
        if (lane == 0) { smm[0] = mm; sms[0] = ss; }
    }
    __syncthreads();
    float lse = smm[0] + logf(sms[0]);

    int l0 = blockIdx.y * 16;
    if (t < 16) wsh[t] = g_log0[l0 + t] + g_log1[l0 + t] - lse;
    __syncthreads();

    int c4 = blockIdx.x * 256 + t;                   // float4 column [0,1024)
    const float4* e = (const float4*)enc;
    float4 acc = make_float4(0.f, 0.f, 0.f, 0.f);
    #pragma unroll
    for (int j = 0; j < 16; ++j) {
        float w = wsh[j];
        float4 ev = __ldcs(e + (size_t)(l0 + j) * (HD / 4) + c4);
        acc.x += w * ev.x; acc.y += w * ev.y;
        acc.z += w * ev.z; acc.w += w * ev.w;
    }
    atomicAdd(&g_attn_applied[c4 * 4 + 0], acc.x);
    atomicAdd(&g_attn_applied[c4 * 4 + 1], acc.y);
    atomicAdd(&g_attn_applied[c4 * 4 + 2], acc.z);
    atomicAdd(&g_attn_applied[c4 * 4 + 3], acc.w);
}

// ---------------- K3: lstm_in += [x, attn_applied] @ W_comb^T + b  (S=2) ----
__global__ __launch_bounds__(256) void comb_kernel(
    const float* __restrict__ W_comb, const float* __restrict__ b_comb,
    const float* __restrict__ x0)
{
    int wid = threadIdx.x >> 5, lane = threadIdx.x & 31;
    int w = blockIdx.x * 8 + wid;          // grid 1024
    int row = w >> 1, seg = w & 1;
    const float4* a = (const float4*)(W_comb + (size_t)row * 2 * HD);
    const float4* b = a + HD / 4;
    int i0 = seg * (HD / 8);
    float s = dot_seg(a, (const float4*)x0, i0, HD / 8, lane)
            + dot_seg(b, (const float4*)g_attn_applied, i0, HD / 8, lane);
    s = warp_sum(s);
    if (lane == 0)
        atomicAdd(&g_lstm_in[row], s + (seg == 0 ? b_comb[row] : 0.0f));
}

// ---------------- K4: gates += W_ih @ lstm_in  (S=2, measured-best) ---------
__global__ __launch_bounds__(256) void ih_kernel(const float* __restrict__ W_ih)
{
    int wid = threadIdx.x >> 5, lane = threadIdx.x & 31;
    int w = blockIdx.x * 8 + wid;          // grid 4096 -> (row, seg), rows [0,4H)
    int row = w >> 1, seg = w & 1;
    const float4* a = (const float4*)(W_ih + (size_t)row * HD);
    int i0 = seg * (HD / 8);
    float s = dot_seg(a, (const float4*)g_lstm_in, i0, HD / 8, lane);
    s = warp_sum(s);
    if (lane == 0) atomicAdd(&g_gates[row], s);
}

// ---------------- K5: LSTM cell elementwise ----------------
__global__ void lstm_kernel(const float* __restrict__ c0) {
    int i = blockIdx.x * blockDim.x + threadIdx.x;
    if (i >= HD) return;
    float ig = g_gates[i];
    float fg = g_gates[i + HD];
    float gg = g_gates[i + 2 * HD];
    float og = g_gates[i + 3 * HD];
    float si = 1.0f / (1.0f + expf(-ig));
    float sf = 1.0f / (1.0f + expf(-fg));
    float so = 1.0f / (1.0f + expf(-og));
    float cn = sf * c0[i] + si * tanhf(gg);
    g_hnew[i] = so * tanhf(cn);
}

// ---------------- K6: word = h_new @ W_out^T + b_out  (measured-best) -------
__global__ __launch_bounds__(256) void wout_kernel(
    const float* __restrict__ W_out, const float* __restrict__ b_out)
{
    int wid = threadIdx.x >> 5, lane = threadIdx.x & 31;
    int row = blockIdx.x * 8 + wid;        // grid 16000
    const float4* a = (const float4*)(W_out + (size_t)row * HD);
    float s = dot_seg(a, (const float4*)g_hnew, 0, HD / 4, lane);
    s = warp_sum(s);
    if (lane == 0) g_word[row] = s + b_out[row];
}

// ---------------- K7: vocab lse stage A (float4, 125 blocks x 256) ----------
__global__ __launch_bounds__(256) void word_lse_partial_kernel() {
    __shared__ float smm[32], sms[32];
    int t = threadIdx.x;
    int lane = t & 31, wid = t >> 5;
    int i = blockIdx.x * 256 + t;          // 125*256 = 32000 float4s = VD
    float4 x = __ldcs((const float4*)g_word + i);
    float m = fmaxf(fmaxf(x.x, x.y), fmaxf(x.z, x.w));
    float s = expf(x.x - m) + expf(x.y - m) + expf(x.z - m) + expf(x.w - m);
    #pragma unroll
    for (int o = 16; o; o >>= 1)
        lse_merge(m, s, __shfl_xor_sync(0xFFFFFFFFu, m, o),
                        __shfl_xor_sync(0xFFFFFFFFu, s, o));
    if (lane == 0) { smm[wid] = m; sms[wid] = s; }
    __syncthreads();
    if (t == 0) {
        float mm = smm[0], ss = sms[0];
        #pragma unroll
        for (int j = 1; j < 8; ++j) lse_merge(mm, ss, smm[j], sms[j]);
        g_pmax[blockIdx.x] = mm; g_psum[blockIdx.x] = ss;
    }
}

// ---------------- K8: combine 125 lse partials (single block) ---------------
__global__ __launch_bounds__(128) void word_lse_final_kernel() {
    __shared__ float smm[4], sms[4];
    int t = threadIdx.x;
    int lane = t & 31, wid = t >> 5;
    float m = (t < NPART) ? g_pmax[t] : -1e30f;
    float s = (t < NPART) ? g_psum[t] : 0.0f;
    #pragma unroll
    for (int o = 16; o; o >>= 1)
        lse_merge(m, s, __shfl_xor_sync(0xFFFFFFFFu, m, o),
                        __shfl_xor_sync(0xFFFFFFFFu, s, o));
    if (lane == 0) { smm[wid] = m; sms[wid] = s; }
    __syncthreads();
    if (t == 0) {
        float mm = smm[0], ss = sms[0];
        #pragma unroll
        for (int j = 1; j < 4; ++j) lse_merge(mm, ss, smm[j], sms[j]);
        g_lse_word = mm + logf(ss);
    }
}

// ---------------- K9: out = word - lse (float4) ----------------
__global__ __launch_bounds__(256) void final_kernel(float* __restrict__ out) {
    int i = blockIdx.x * 256 + threadIdx.x;          // 125 blocks x 256 float4s
    float lse = g_lse_word;
    float4 x = ((const float4*)g_word)[i];
    x.x -= lse; x.y -= lse; x.z -= lse; x.w -= lse;
    ((float4*)out)[i] = x;
}

// ======================================================================
extern "C" void kernel_launch(void* const* d_in, const int* in_sizes, int n_in,
                              void* d_out, int out_size) {
    const float* enc    = (const float*)d_in[0];
    const float* h0     = (const float*)d_in[1];
    const float* c0     = (const float*)d_in[2];
    const float* x0     = (const float*)d_in[3];
    const float* W_attn = (const float*)d_in[4];
    const float* b_attn = (const float*)d_in[5];
    const float* W_comb = (const float*)d_in[6];
    const float* b_comb = (const float*)d_in[7];
    const float* W_ih   = (const float*)d_in[8];
    const float* b_ih   = (const float*)d_in[9];
    const float* W_hh   = (const float*)d_in[10];
    const float* b_hh   = (const float*)d_in[11];
    const float* W_out  = (const float*)d_in[12];
    const float* b_out  = (const float*)d_in[13];
    float* out = (float*)d_out;

    const int TPB = 256;

    // K1: attn logits (S=2, 1024 blks) + W_hh@h base (2048 blks) + zeroing
    phase1_kernel<<<NA_BLOCKS + (4 * HD) / 8, TPB>>>(W_attn, b_attn, h0, x0,
                                                     W_hh, b_hh, b_ih);
    // K2: per-block LSE + attn_applied   (64 MB, 1024 blocks)
    attn_applied_kernel<<<dim3(HD / 4 / TPB, 256), TPB>>>(enc);
    // K3: lstm_in = [x, attn_applied] @ W_comb^T + b   (S=2, 1024 blocks)
    comb_kernel<<<(2 * HD) / 8, TPB>>>(W_comb, b_comb, x0);
    // K4: gates += W_ih @ lstm_in   (S=2, 4096 blocks — measured best)
    ih_kernel<<<(2 * 4 * HD) / 8, TPB>>>(W_ih);
    // K5: LSTM cell
    lstm_kernel<<<HD / TPB, TPB>>>(c0);
    // K6: word = h_new @ W_out^T + b_out   (2.1 GB, 16000 blocks)
    wout_kernel<<<VD / 8, TPB>>>(W_out, b_out);
    // K7-8: logsumexp over V (float4 stage A: 125 blocks)
    word_lse_partial_kernel<<<NPART, TPB>>>();
    word_lse_final_kernel<<<1, 128>>>();
    // K9: out = word - lse (float4)
    final_kernel<<<NPART, TPB>>>(out);
}